// round 9
// baseline (speedup 1.0000x reference)
#include <cuda_runtime.h>
#include <cuda_fp16.h>
#include <cstdint>

// SimpleGNN (2-layer GCN), N=200000, E=6.4M, idx int32.
// Round 7: bucketed edge partition + SMEM aggregation. NO global float REDs.
//   passA:  per-block histogram of dst-buckets (bucket = dst>>9, 512 nodes ea)
//   colscan: per-bucket exclusive scan over block counts -> per-block bases
//   bstart: exclusive scan of bucket totals
//   passB:  scatter packed edges (src<<9 | dst_local) into bucket-sorted buf
//   degS:   per-bucket smem int counters -> d_deg (plain stores)
//   scale:  dinv + fp16/fp32 pre-scaled features
//   scat1S: block-per-bucket, gather fp16 rows, smem f32 atomicAdd, flush acc1
//   node:   per-node MLP (W1+relu+W2), writes g (f32 + fp16)
//   scat2S: block-per-bucket layer-2 aggregation, fused bias/normalize/output
// Scratch in __device__ globals; launches only (graph-capturable).

#define MAXN   200000
#define MAXE   6400000
#define BSH    9
#define BNODES 512                      // nodes per bucket
#define NBMAX  ((MAXN + BNODES - 1) / BNODES)   // 391
#define EPB    1024                     // edges per block in passA/passB
#define NBLKA  ((MAXE + EPB - 1) / EPB)         // 6250
#define ROWP   12
#define XH     16

__device__ __half    d_xsh [(size_t)MAXN * XH];
__device__ float     d_xs32[(size_t)MAXN * ROWP];
__device__ float     d_acc1[(size_t)MAXN * ROWP];
__device__ float     d_dinv[MAXN];
__device__ float     d_g   [(size_t)MAXN * 2];
__device__ __half2   d_gh  [MAXN];
__device__ int       d_deg [MAXN];
__device__ int       d_blkoff[(size_t)NBMAX * NBLKA];  // [bucket][block]
__device__ int       d_btot  [NBMAX + 1];
__device__ int       d_bstart[NBMAX + 2];
__device__ uint32_t  d_ebuf  [MAXE];

// ------------------------------------------------------------------ passA
__global__ __launch_bounds__(256) void k_passA(const int* __restrict__ dst,
                                               int E, int NB, int nblk) {
    __shared__ int cnt[NBMAX];
    int tid = threadIdx.x, blk = blockIdx.x;
    for (int t = tid; t < NB; t += 256) cnt[t] = 0;
    __syncthreads();
    int base = blk * EPB + tid * 4;
    if (base + 3 < E) {
        int4 d4 = *(const int4*)(dst + base);
        atomicAdd(&cnt[d4.x >> BSH], 1);
        atomicAdd(&cnt[d4.y >> BSH], 1);
        atomicAdd(&cnt[d4.z >> BSH], 1);
        atomicAdd(&cnt[d4.w >> BSH], 1);
    } else {
        for (int k = 0; k < 4; k++) {
            int e = base + k;
            if (e < E) atomicAdd(&cnt[dst[e] >> BSH], 1);
        }
    }
    __syncthreads();
    for (int t = tid; t < NB; t += 256)
        d_blkoff[(size_t)t * nblk + blk] = cnt[t];
}

// ------------------------------------------------------- per-bucket colscan
// Exclusive scan of block counts within each bucket; total -> d_btot.
__global__ __launch_bounds__(256) void k_colscan(int nblk) {
    __shared__ int sm[256];
    int b = blockIdx.x, t = threadIdx.x;
    int C = (nblk + 255) / 256;
    int* col = d_blkoff + (size_t)b * nblk;
    int s = 0;
    for (int k = 0; k < C; k++) {
        int i = t * C + k;
        if (i < nblk) s += col[i];
    }
    sm[t] = s;
    __syncthreads();
    for (int off = 1; off < 256; off <<= 1) {
        int v = (t >= off) ? sm[t - off] : 0;
        __syncthreads();
        sm[t] += v;
        __syncthreads();
    }
    int run = sm[t] - s;                      // exclusive prefix
    for (int k = 0; k < C; k++) {
        int i = t * C + k;
        if (i < nblk) { int v = col[i]; col[i] = run; run += v; }
    }
    if (t == 0) d_btot[b] = sm[255];
}

// ------------------------------------------------------- bucket start scan
__global__ __launch_bounds__(512) void k_bstart(int NB) {
    __shared__ int sm[512];
    int t = threadIdx.x;
    int v = (t < NB) ? d_btot[t] : 0;
    sm[t] = v;
    __syncthreads();
    for (int off = 1; off < 512; off <<= 1) {
        int a = (t >= off) ? sm[t - off] : 0;
        __syncthreads();
        sm[t] += a;
        __syncthreads();
    }
    if (t < NB) d_bstart[t] = sm[t] - v;      // exclusive
    if (t == 0) d_bstart[NB] = sm[511];       // total = E
}

// ------------------------------------------------------------------ passB
__global__ __launch_bounds__(256) void k_passB(const int* __restrict__ idx,
                                               int E, int NB, int nblk) {
    __shared__ int cur[NBMAX];
    int tid = threadIdx.x, blk = blockIdx.x;
    for (int t = tid; t < NB; t += 256)
        cur[t] = d_bstart[t] + d_blkoff[(size_t)t * nblk + blk];
    __syncthreads();
    int base = blk * EPB + tid * 4;
    if (base + 3 < E) {
        int4 s4 = *(const int4*)(idx + base);
        int4 d4 = *(const int4*)(idx + (size_t)E + base);
        int ss[4] = {s4.x, s4.y, s4.z, s4.w};
        int dd[4] = {d4.x, d4.y, d4.z, d4.w};
#pragma unroll
        for (int k = 0; k < 4; k++) {
            int b = dd[k] >> BSH;
            int pos = atomicAdd(&cur[b], 1);
            d_ebuf[pos] = ((uint32_t)ss[k] << BSH) | (uint32_t)(dd[k] & (BNODES - 1));
        }
    } else {
        for (int k = 0; k < 4; k++) {
            int e = base + k;
            if (e < E) {
                int s = idx[e], d = idx[(size_t)E + e];
                int pos = atomicAdd(&cur[d >> BSH], 1);
                d_ebuf[pos] = ((uint32_t)s << BSH) | (uint32_t)(d & (BNODES - 1));
            }
        }
    }
}

// ------------------------------------------------------------------- degS
__global__ __launch_bounds__(512) void k_degS(int n) {
    __shared__ int c[BNODES];
    int b = blockIdx.x, t = threadIdx.x;
    c[t] = 0;
    __syncthreads();
    int start = d_bstart[b], end = d_bstart[b + 1];
    for (int i = start + t; i < end; i += 512)
        atomicAdd(&c[d_ebuf[i] & (BNODES - 1)], 1);
    __syncthreads();
    int node = b * BNODES + t;
    if (node < n) d_deg[node] = c[t];
}

// ------------------------------------------------------------------ scale
__global__ __launch_bounds__(256) void k_scale(const float* __restrict__ x, int n) {
    int i = blockIdx.x * blockDim.x + threadIdx.x;
    if (i >= n) return;
    float dv = rsqrtf((float)(d_deg[i] + 1));
    d_dinv[i] = dv;
    const float* xi = x + (size_t)i * 10;
    float* xo = d_xs32 + (size_t)i * ROWP;
    float v[10];
#pragma unroll
    for (int k = 0; k < 10; k++) { v[k] = xi[k] * dv; xo[k] = v[k]; }
    __half2 h[5];
#pragma unroll
    for (int k = 0; k < 5; k++) h[k] = __floats2half2_rn(v[2 * k], v[2 * k + 1]);
    uint4 pk;
    pk.x = *(uint32_t*)&h[0]; pk.y = *(uint32_t*)&h[1];
    pk.z = *(uint32_t*)&h[2]; pk.w = *(uint32_t*)&h[3];
    *(uint4*)(d_xsh + (size_t)i * XH) = pk;
    *(uint32_t*)(d_xsh + (size_t)i * XH + 8) = *(uint32_t*)&h[4];
}

// ----------------------------------------------------------------- scat1S
// Block per bucket: gather fp16 xs rows, fp32 smem atomicAdd, plain flush.
__global__ __launch_bounds__(512) void k_scat1S(int n) {
    __shared__ float sacc[BNODES * 10];     // 20 KB
    int b = blockIdx.x, t = threadIdx.x;
    for (int i = t; i < BNODES * 10; i += 512) sacc[i] = 0.0f;
    __syncthreads();
    int start = d_bstart[b], end = d_bstart[b + 1];
    for (int i = start + t; i < end; i += 512) {
        uint32_t p = d_ebuf[i];
        int s = p >> BSH;
        int l = p & (BNODES - 1);
        const __half* ps = d_xsh + (size_t)s * XH;
        uint4    u  = *(const uint4*)(ps);
        uint32_t ub = *(const uint32_t*)(ps + 8);
        float2 f0 = __half22float2(*(__half2*)&u.x);
        float2 f1 = __half22float2(*(__half2*)&u.y);
        float2 f2 = __half22float2(*(__half2*)&u.z);
        float2 f3 = __half22float2(*(__half2*)&u.w);
        float2 f4 = __half22float2(*(__half2*)&ub);
        float* pa = sacc + l * 10;
        atomicAdd(pa + 0, f0.x); atomicAdd(pa + 1, f0.y);
        atomicAdd(pa + 2, f1.x); atomicAdd(pa + 3, f1.y);
        atomicAdd(pa + 4, f2.x); atomicAdd(pa + 5, f2.y);
        atomicAdd(pa + 6, f3.x); atomicAdd(pa + 7, f3.y);
        atomicAdd(pa + 8, f4.x); atomicAdd(pa + 9, f4.y);
    }
    __syncthreads();
    int node = b * BNODES + t;
    if (node < n) {
        const float* pa = sacc + t * 10;
        float* pd = d_acc1 + (size_t)node * ROWP;
        *(float4*)(pd)     = make_float4(pa[0], pa[1], pa[2], pa[3]);
        *(float4*)(pd + 4) = make_float4(pa[4], pa[5], pa[6], pa[7]);
        *(float2*)(pd + 8) = make_float2(pa[8], pa[9]);
    }
}

// ------------------------------------------------------------------- node
__global__ __launch_bounds__(256) void k_node(const float* __restrict__ W1,
                                              const float* __restrict__ b1,
                                              const float* __restrict__ W2, int n) {
    __shared__ float sW1[160], sb1[16], sW2[32];
    int t = threadIdx.x;
    if (t < 160) sW1[t] = W1[t];
    if (t < 16)  sb1[t] = b1[t];
    if (t < 32)  sW2[t] = W2[t];
    __syncthreads();
    int i = blockIdx.x * blockDim.x + t;
    if (i >= n) return;
    float dv = d_dinv[i];
    const float* pa = d_acc1 + (size_t)i * ROWP;
    const float* px = d_xs32 + (size_t)i * ROWP;
    float tt[10];
#pragma unroll
    for (int k = 0; k < 10; k++) tt[k] = (pa[k] + px[k]) * dv;  // (A_hat x)[i]
    float g0 = 0.0f, g1 = 0.0f;
#pragma unroll
    for (int j = 0; j < 16; j++) {
        float h = sb1[j];
#pragma unroll
        for (int k = 0; k < 10; k++) h = fmaf(tt[k], sW1[k * 16 + j], h);
        h = fmaxf(h, 0.0f);
        g0 = fmaf(h, sW2[j * 2 + 0], g0);
        g1 = fmaf(h, sW2[j * 2 + 1], g1);
    }
    g0 *= dv; g1 *= dv;                      // pre-scaled msg for layer 2
    d_g[2 * (size_t)i + 0] = g0;
    d_g[2 * (size_t)i + 1] = g1;
    d_gh[i] = __floats2half2_rn(g0, g1);
}

// ----------------------------------------------------------------- scat2S
// Block per bucket: layer-2 aggregation in smem, fused normalize+bias+output.
__global__ __launch_bounds__(512) void k_scat2S(const float* __restrict__ b2,
                                                float* __restrict__ out, int n) {
    __shared__ float s2[BNODES * 2];        // 4 KB
    int b = blockIdx.x, t = threadIdx.x;
    s2[t] = 0.0f; s2[t + 512] = 0.0f;
    __syncthreads();
    int start = d_bstart[b], end = d_bstart[b + 1];
    for (int i = start + t; i < end; i += 512) {
        uint32_t p = d_ebuf[i];
        int s = p >> BSH;
        int l = p & (BNODES - 1);
        float2 v = __half22float2(d_gh[s]);
        atomicAdd(&s2[l * 2 + 0], v.x);
        atomicAdd(&s2[l * 2 + 1], v.y);
    }
    __syncthreads();
    int node = b * BNODES + t;
    if (node < n) {
        float dv = d_dinv[node];
        float2 g = *(const float2*)(d_g + 2 * (size_t)node);
        out[2 * (size_t)node + 0] = dv * (s2[t * 2 + 0] + g.x) + __ldg(b2);
        out[2 * (size_t)node + 1] = dv * (s2[t * 2 + 1] + g.y) + __ldg(b2 + 1);
    }
}

extern "C" void kernel_launch(void* const* d_in, const int* in_sizes, int n_in,
                              void* d_out, int out_size) {
    const float* x  = (const float*)d_in[0];
    const int*   ei = (const int*)d_in[1];     // int32 (jax x64 disabled)
    const float* W1 = (const float*)d_in[2];
    const float* b1 = (const float*)d_in[3];
    const float* W2 = (const float*)d_in[4];
    const float* b2 = (const float*)d_in[5];
    float* out = (float*)d_out;

    int n = in_sizes[0] / 10;
    int E = in_sizes[1] / 2;

    int NB   = (n + BNODES - 1) >> BSH;        // 391
    int nblk = (E + EPB - 1) / EPB;            // 6250
    int gn   = (n + 255) / 256;

    k_passA  <<<nblk, 256>>>(ei + E, E, NB, nblk);
    k_colscan<<<NB,   256>>>(nblk);
    k_bstart <<<1,    512>>>(NB);
    k_passB  <<<nblk, 256>>>(ei, E, NB, nblk);
    k_degS   <<<NB,   512>>>(n);
    k_scale  <<<gn,   256>>>(x, n);
    k_scat1S <<<NB,   512>>>(n);
    k_node   <<<gn,   256>>>(W1, b1, W2, n);
    k_scat2S <<<NB,   512>>>(b2, out, n);
}

// round 14
// speedup vs baseline: 1.5284x; 1.5284x over previous
#include <cuda_runtime.h>
#include <cuda_fp16.h>
#include <cstdint>

// SimpleGNN (2-layer GCN), N=200000, E=6.4M, idx int32.
// R12 = R6 scatter pipeline + single-sector mixed accumulator for layer 1.
//  - deg pass (int red, 4 edges/thread) -> dinv = rsqrt(deg+1)
//  - layer1 aggregate-first: scatter fp16 xs = x*dinv rows (one 32B sector
//    gather). Accumulator row = 32B: features 0-5 f32 (v4+v2 REDs),
//    features 6-9 f16 (v2.f16x2 RED, payload straight from the gather).
//    => exactly ONE RMW sector per edge (was 2).
//  - per-node MLP: t = dinv*(acc1+self); h1=relu(t@W1+b1); g=(h1@W2)*dinv
//  - layer2 scatter: fp16 4B gather + f32 v2 RED; k_out adds bias/norm.
// Scratch in __device__ globals; launches only (graph-capturable).

#define MAXN 200000
#define ROWA 8      // acc1 row stride in floats (32B = one L2 sector)
#define XH   16     // xs row stride in halves (32B = one L2 sector)

__device__ __half  d_xsh [(size_t)MAXN * XH];
__device__ float   d_xs32[(size_t)MAXN * 12];
__device__ __align__(128) float d_acc1[(size_t)MAXN * ROWA];  // [6xf32|4xf16]
__device__ float   d_dinv[MAXN];
__device__ float   d_g   [(size_t)MAXN * 2];   // f32 (self term, exact)
__device__ __half2 d_gh  [MAXN];               // fp16 (edge gather payload)
__device__ float   d_acc2[(size_t)MAXN * 2];
__device__ int     d_deg [MAXN];

__device__ __forceinline__ void red_add_v4(float* p, float4 v) {
    asm volatile("red.global.add.v4.f32 [%0], {%1,%2,%3,%4};"
                 :: "l"(p), "f"(v.x), "f"(v.y), "f"(v.z), "f"(v.w) : "memory");
}
__device__ __forceinline__ void red_add_v2(float* p, float2 v) {
    asm volatile("red.global.add.v2.f32 [%0], {%1,%2};"
                 :: "l"(p), "f"(v.x), "f"(v.y) : "memory");
}
__device__ __forceinline__ void red_add_v2h(void* p, uint32_t h0, uint32_t h1) {
    asm volatile("red.global.add.noftz.v2.f16x2 [%0], {%1,%2};"
                 :: "l"(p), "r"(h0), "r"(h1) : "memory");
}

__global__ __launch_bounds__(256) void k_zero_deg(int n) {
    int i = blockIdx.x * blockDim.x + threadIdx.x;
    if (i < n) d_deg[i] = 0;
}

// In-degree, 4 edges/thread (int4 index loads).
__global__ __launch_bounds__(256) void k_deg(const int* __restrict__ dst, int E) {
    int t = blockIdx.x * blockDim.x + threadIdx.x;
    int base = t * 4;
    if (base + 3 < E) {
        int4 d4 = *(const int4*)(dst + base);
        atomicAdd(&d_deg[d4.x], 1);
        atomicAdd(&d_deg[d4.y], 1);
        atomicAdd(&d_deg[d4.z], 1);
        atomicAdd(&d_deg[d4.w], 1);
    } else {
        for (int k = 0; k < 4; k++) {
            int e = base + k;
            if (e < E) atomicAdd(&d_deg[dst[e]], 1);
        }
    }
}

// dinv + pre-scaled features (fp16 row for gather, fp32 row for self term).
// Also zeros acc1 (32B row) and acc2.
__global__ __launch_bounds__(256) void k_scale(const float* __restrict__ x, int n) {
    int i = blockIdx.x * blockDim.x + threadIdx.x;
    if (i >= n) return;
    float dv = rsqrtf((float)(d_deg[i] + 1));
    d_dinv[i] = dv;
    const float* xi = x + (size_t)i * 10;
    float* xo = d_xs32 + (size_t)i * 12;
    float v[10];
#pragma unroll
    for (int k = 0; k < 10; k++) { v[k] = xi[k] * dv; xo[k] = v[k]; }
    __half2 h[5];
#pragma unroll
    for (int k = 0; k < 5; k++) h[k] = __floats2half2_rn(v[2 * k], v[2 * k + 1]);
    uint4 pk;
    pk.x = *(uint32_t*)&h[0]; pk.y = *(uint32_t*)&h[1];
    pk.z = *(uint32_t*)&h[2]; pk.w = *(uint32_t*)&h[3];
    *(uint4*)(d_xsh + (size_t)i * XH) = pk;
    *(uint32_t*)(d_xsh + (size_t)i * XH + 8) = *(uint32_t*)&h[4];
    // zero accumulators
    float4 z4 = make_float4(0.f, 0.f, 0.f, 0.f);
    float* a1 = d_acc1 + (size_t)i * ROWA;
    *(float4*)(a1) = z4; *(float4*)(a1 + 4) = z4;     // f16 lanes zeroed too
    *(float2*)(d_acc2 + 2 * (size_t)i) = make_float2(0.f, 0.f);
}

// Layer-1 edge scatter, 2 edges/thread: one 32B sector gather, one 32B
// RMW sector: v4.f32 (feat 0-3) + v2.f32 (4-5) + v2.f16x2 (6-9, raw halves).
__global__ __launch_bounds__(256) void k_scat1(const int* __restrict__ idx, int E) {
    int t = blockIdx.x * blockDim.x + threadIdx.x;
    int base = t * 2;
    int s0, s1, d0, d1; int cnt;
    if (base + 1 < E) {
        int2 sp = *(const int2*)(idx + base);
        int2 dp = *(const int2*)(idx + (size_t)E + base);
        s0 = sp.x; s1 = sp.y; d0 = dp.x; d1 = dp.y; cnt = 2;
    } else if (base < E) {
        s0 = idx[base]; d0 = idx[(size_t)E + base]; s1 = d1 = 0; cnt = 1;
    } else return;
#pragma unroll
    for (int k = 0; k < 2; k++) {
        if (k >= cnt) break;
        int s = k ? s1 : s0;
        int d = k ? d1 : d0;
        const __half* ps = d_xsh + (size_t)s * XH;
        uint4    u  = *(const uint4*)(ps);       // v0..v7 as 4x half2
        uint32_t ub = *(const uint32_t*)(ps + 8); // v8,v9
        float2 f0 = __half22float2(*(__half2*)&u.x);   // v0,v1
        float2 f1 = __half22float2(*(__half2*)&u.y);   // v2,v3
        float2 f2 = __half22float2(*(__half2*)&u.z);   // v4,v5
        float* pd = d_acc1 + (size_t)d * ROWA;
        red_add_v4(pd,     make_float4(f0.x, f0.y, f1.x, f1.y));
        red_add_v2(pd + 4, make_float2(f2.x, f2.y));
        red_add_v2h(pd + 6, u.w, ub);            // v6..v9 accumulate in fp16
    }
}

// Per-node MLP; reads mixed accumulator row; writes g (f32 + fp16).
__global__ __launch_bounds__(256) void k_node(const float* __restrict__ W1,
                                              const float* __restrict__ b1,
                                              const float* __restrict__ W2, int n) {
    __shared__ float sW1[160], sb1[16], sW2[32];
    int t = threadIdx.x;
    if (t < 160) sW1[t] = W1[t];
    if (t < 16)  sb1[t] = b1[t];
    if (t < 32)  sW2[t] = W2[t];
    __syncthreads();
    int i = blockIdx.x * blockDim.x + t;
    if (i >= n) return;
    float dv = d_dinv[i];
    const float* pa = d_acc1 + (size_t)i * ROWA;
    const float* px = d_xs32 + (size_t)i * 12;
    float4 qa = *(const float4*)(pa);
    float2 qb = *(const float2*)(pa + 4);
    uint32_t hw1 = *(const uint32_t*)(pa + 6);
    uint32_t hw2 = *(const uint32_t*)(pa + 7);
    float2 q67 = __half22float2(*(__half2*)&hw1);
    float2 q89 = __half22float2(*(__half2*)&hw2);
    float acc[10] = {qa.x, qa.y, qa.z, qa.w, qb.x, qb.y,
                     q67.x, q67.y, q89.x, q89.y};
    float tt[10];
#pragma unroll
    for (int k = 0; k < 10; k++) tt[k] = (acc[k] + px[k]) * dv;  // (A_hat x)[i]
    float g0 = 0.0f, g1 = 0.0f;
#pragma unroll
    for (int j = 0; j < 16; j++) {
        float h = sb1[j];
#pragma unroll
        for (int k = 0; k < 10; k++) h = fmaf(tt[k], sW1[k * 16 + j], h);
        h = fmaxf(h, 0.0f);
        g0 = fmaf(h, sW2[j * 2 + 0], g0);
        g1 = fmaf(h, sW2[j * 2 + 1], g1);
    }
    g0 *= dv; g1 *= dv;                      // pre-scaled msg for layer 2
    d_g[2 * (size_t)i + 0] = g0;
    d_g[2 * (size_t)i + 1] = g1;
    d_gh[i] = __floats2half2_rn(g0, g1);
}

// Layer-2 edge scatter, 4 edges/thread: fp16 4B gather + f32 v2 RED.
__global__ __launch_bounds__(256) void k_scat2(const int* __restrict__ idx, int E) {
    int t = blockIdx.x * blockDim.x + threadIdx.x;
    int base = t * 4;
    if (base + 3 < E) {
        int4 sp = *(const int4*)(idx + base);
        int4 dp = *(const int4*)(idx + (size_t)E + base);
        float2 v0 = __half22float2(d_gh[sp.x]);
        float2 v1 = __half22float2(d_gh[sp.y]);
        float2 v2 = __half22float2(d_gh[sp.z]);
        float2 v3 = __half22float2(d_gh[sp.w]);
        red_add_v2(d_acc2 + 2 * (size_t)dp.x, v0);
        red_add_v2(d_acc2 + 2 * (size_t)dp.y, v1);
        red_add_v2(d_acc2 + 2 * (size_t)dp.z, v2);
        red_add_v2(d_acc2 + 2 * (size_t)dp.w, v3);
    } else {
        for (int k = 0; k < 4; k++) {
            int e = base + k;
            if (e < E) {
                int s = idx[e];
                int d = idx[(size_t)E + e];
                red_add_v2(d_acc2 + 2 * (size_t)d, __half22float2(d_gh[s]));
            }
        }
    }
}

// Final: out = dinv*(acc2 + self_f32) + b2
__global__ __launch_bounds__(256) void k_out(const float* __restrict__ b2,
                                             float* __restrict__ out, int n) {
    int i = blockIdx.x * blockDim.x + threadIdx.x;
    if (i >= n) return;
    float dv = d_dinv[i];
    float2 a = *(const float2*)(d_acc2 + 2 * (size_t)i);
    float2 g = *(const float2*)(d_g + 2 * (size_t)i);
    out[2 * (size_t)i + 0] = dv * (a.x + g.x) + __ldg(b2);
    out[2 * (size_t)i + 1] = dv * (a.y + g.y) + __ldg(b2 + 1);
}

extern "C" void kernel_launch(void* const* d_in, const int* in_sizes, int n_in,
                              void* d_out, int out_size) {
    const float* x  = (const float*)d_in[0];
    const int*   ei = (const int*)d_in[1];     // int32 (jax x64 disabled)
    const float* W1 = (const float*)d_in[2];
    const float* b1 = (const float*)d_in[3];
    const float* W2 = (const float*)d_in[4];
    const float* b2 = (const float*)d_in[5];
    float* out = (float*)d_out;

    int n = in_sizes[0] / 10;
    int E = in_sizes[1] / 2;

    const int TB = 256;
    int gn  = (n + TB - 1) / TB;
    int ge2 = ((E + 1) / 2 + TB - 1) / TB;
    int ge4 = ((E + 3) / 4 + TB - 1) / TB;

    k_zero_deg<<<gn,  TB>>>(n);
    k_deg     <<<ge4, TB>>>(ei + E, E);     // dst row
    k_scale   <<<gn,  TB>>>(x, n);
    k_scat1   <<<ge2, TB>>>(ei, E);
    k_node    <<<gn,  TB>>>(W1, b1, W2, n);
    k_scat2   <<<ge4, TB>>>(ei, E);
    k_out     <<<gn,  TB>>>(b2, out, n);
}

// round 17
// speedup vs baseline: 1.7591x; 1.1509x over previous
#include <cuda_runtime.h>
#include <cuda_fp16.h>
#include <cstdint>

// SimpleGNN (2-layer GCN), N=200000, E=6.4M, idx int32.
// R15 = scatter pipeline with TWO REDs per edge in layer 1:
//   acc1 row (32B): [8 x f16 (feat v2..v9) | 2 x f32 (v0,v1) | pad]
//   per edge: red.v4.f16x2 (v2..v9, payload direct from fp16 gather)
//           + red.v2.f32   (v0,v1)
// LTS access model: scat1 = 1 gather + 2 RED + 0.25 idx = 3.25/edge (was 4.25).
//  - deg pass (int red, 4 edges/thread) -> dinv = rsqrt(deg+1)
//  - per-node MLP: t = dinv*(acc1+self); h1=relu(t@W1+b1); g=(h1@W2)*dinv
//  - layer2 scatter: fp16 4B gather + f32 v2 RED; k_out adds bias/norm.
// Scratch in __device__ globals; launches only (graph-capturable).

#define MAXN 200000
#define ROWA 8      // acc1 row stride in floats (32B)
#define XH   16     // xs row stride in halves (32B = one L2 sector)

__device__ __half  d_xsh [(size_t)MAXN * XH];
__device__ float   d_xs32[(size_t)MAXN * 12];
__device__ __align__(128) float d_acc1[(size_t)MAXN * ROWA]; // [8xf16|2xf32|pad]
__device__ float   d_dinv[MAXN];
__device__ float   d_g   [(size_t)MAXN * 2];   // f32 (self term, exact)
__device__ __half2 d_gh  [MAXN];               // fp16 (edge gather payload)
__device__ float   d_acc2[(size_t)MAXN * 2];
__device__ int     d_deg [MAXN];

__device__ __forceinline__ void red_add_v2(float* p, float2 v) {
    asm volatile("red.global.add.v2.f32 [%0], {%1,%2};"
                 :: "l"(p), "f"(v.x), "f"(v.y) : "memory");
}
__device__ __forceinline__ void red_add_v4h(void* p, uint32_t h0, uint32_t h1,
                                            uint32_t h2, uint32_t h3) {
    asm volatile("red.global.add.noftz.v4.f16x2 [%0], {%1,%2,%3,%4};"
                 :: "l"(p), "r"(h0), "r"(h1), "r"(h2), "r"(h3) : "memory");
}

__global__ __launch_bounds__(256) void k_zero_deg(int n) {
    int i = blockIdx.x * blockDim.x + threadIdx.x;
    if (i < n) d_deg[i] = 0;
}

// In-degree, 4 edges/thread (int4 index loads).
__global__ __launch_bounds__(256) void k_deg(const int* __restrict__ dst, int E) {
    int t = blockIdx.x * blockDim.x + threadIdx.x;
    int base = t * 4;
    if (base + 3 < E) {
        int4 d4 = *(const int4*)(dst + base);
        atomicAdd(&d_deg[d4.x], 1);
        atomicAdd(&d_deg[d4.y], 1);
        atomicAdd(&d_deg[d4.z], 1);
        atomicAdd(&d_deg[d4.w], 1);
    } else {
        for (int k = 0; k < 4; k++) {
            int e = base + k;
            if (e < E) atomicAdd(&d_deg[dst[e]], 1);
        }
    }
}

// dinv + pre-scaled features (fp16 row for gather, fp32 row for self term).
// Also zeros acc1 (32B row) and acc2.
__global__ __launch_bounds__(256) void k_scale(const float* __restrict__ x, int n) {
    int i = blockIdx.x * blockDim.x + threadIdx.x;
    if (i >= n) return;
    float dv = rsqrtf((float)(d_deg[i] + 1));
    d_dinv[i] = dv;
    const float* xi = x + (size_t)i * 10;
    float* xo = d_xs32 + (size_t)i * 12;
    float v[10];
#pragma unroll
    for (int k = 0; k < 10; k++) { v[k] = xi[k] * dv; xo[k] = v[k]; }
    __half2 h[5];
#pragma unroll
    for (int k = 0; k < 5; k++) h[k] = __floats2half2_rn(v[2 * k], v[2 * k + 1]);
    uint4 pk;
    pk.x = *(uint32_t*)&h[0]; pk.y = *(uint32_t*)&h[1];
    pk.z = *(uint32_t*)&h[2]; pk.w = *(uint32_t*)&h[3];
    *(uint4*)(d_xsh + (size_t)i * XH) = pk;
    *(uint32_t*)(d_xsh + (size_t)i * XH + 8) = *(uint32_t*)&h[4];
    // zero accumulators
    float4 z4 = make_float4(0.f, 0.f, 0.f, 0.f);
    float* a1 = d_acc1 + (size_t)i * ROWA;
    *(float4*)(a1) = z4; *(float4*)(a1 + 4) = z4;
    *(float2*)(d_acc2 + 2 * (size_t)i) = make_float2(0.f, 0.f);
}

// Layer-1 edge scatter, 2 edges/thread.
// Row halves: u.x=(v0,v1) u.y=(v2,v3) u.z=(v4,v5) u.w=(v6,v7) ub=(v8,v9).
// REDs: v4.f16x2 {u.y,u.z,u.w,ub} -> acc row +0 ; v2.f32 {v0,v1} -> +16B.
__global__ __launch_bounds__(256) void k_scat1(const int* __restrict__ idx, int E) {
    int t = blockIdx.x * blockDim.x + threadIdx.x;
    int base = t * 2;
    int s0, s1, d0, d1; int cnt;
    if (base + 1 < E) {
        int2 sp = *(const int2*)(idx + base);
        int2 dp = *(const int2*)(idx + (size_t)E + base);
        s0 = sp.x; s1 = sp.y; d0 = dp.x; d1 = dp.y; cnt = 2;
    } else if (base < E) {
        s0 = idx[base]; d0 = idx[(size_t)E + base]; s1 = d1 = 0; cnt = 1;
    } else return;
#pragma unroll
    for (int k = 0; k < 2; k++) {
        if (k >= cnt) break;
        int s = k ? s1 : s0;
        int d = k ? d1 : d0;
        const __half* ps = d_xsh + (size_t)s * XH;
        uint4    u  = *(const uint4*)(ps);
        uint32_t ub = *(const uint32_t*)(ps + 8);
        float2 f0 = __half22float2(*(__half2*)&u.x);   // v0,v1 -> f32
        float* pd = d_acc1 + (size_t)d * ROWA;
        red_add_v4h(pd, u.y, u.z, u.w, ub);            // v2..v9 in fp16
        red_add_v2(pd + 4, make_float2(f0.x, f0.y));   // v0,v1 in f32 (+16B)
    }
}

// Per-node MLP; reads mixed accumulator row; writes g (f32 + fp16).
__global__ __launch_bounds__(256) void k_node(const float* __restrict__ W1,
                                              const float* __restrict__ b1,
                                              const float* __restrict__ W2, int n) {
    __shared__ float sW1[160], sb1[16], sW2[32];
    int t = threadIdx.x;
    if (t < 160) sW1[t] = W1[t];
    if (t < 16)  sb1[t] = b1[t];
    if (t < 32)  sW2[t] = W2[t];
    __syncthreads();
    int i = blockIdx.x * blockDim.x + t;
    if (i >= n) return;
    float dv = d_dinv[i];
    const float* pa = d_acc1 + (size_t)i * ROWA;
    const float* px = d_xs32 + (size_t)i * 12;
    uint4 hh = *(const uint4*)(pa);           // v2..v9 as 4x half2
    float2 p23 = __half22float2(*(__half2*)&hh.x);
    float2 p45 = __half22float2(*(__half2*)&hh.y);
    float2 p67 = __half22float2(*(__half2*)&hh.z);
    float2 p89 = __half22float2(*(__half2*)&hh.w);
    float2 p01 = *(const float2*)(pa + 4);    // v0,v1 f32
    float acc[10] = {p01.x, p01.y, p23.x, p23.y, p45.x, p45.y,
                     p67.x, p67.y, p89.x, p89.y};
    float tt[10];
#pragma unroll
    for (int k = 0; k < 10; k++) tt[k] = (acc[k] + px[k]) * dv;  // (A_hat x)[i]
    float g0 = 0.0f, g1 = 0.0f;
#pragma unroll
    for (int j = 0; j < 16; j++) {
        float h = sb1[j];
#pragma unroll
        for (int k = 0; k < 10; k++) h = fmaf(tt[k], sW1[k * 16 + j], h);
        h = fmaxf(h, 0.0f);
        g0 = fmaf(h, sW2[j * 2 + 0], g0);
        g1 = fmaf(h, sW2[j * 2 + 1], g1);
    }
    g0 *= dv; g1 *= dv;                      // pre-scaled msg for layer 2
    d_g[2 * (size_t)i + 0] = g0;
    d_g[2 * (size_t)i + 1] = g1;
    d_gh[i] = __floats2half2_rn(g0, g1);
}

// Layer-2 edge scatter, 4 edges/thread: fp16 4B gather + f32 v2 RED.
__global__ __launch_bounds__(256) void k_scat2(const int* __restrict__ idx, int E) {
    int t = blockIdx.x * blockDim.x + threadIdx.x;
    int base = t * 4;
    if (base + 3 < E) {
        int4 sp = *(const int4*)(idx + base);
        int4 dp = *(const int4*)(idx + (size_t)E + base);
        float2 v0 = __half22float2(d_gh[sp.x]);
        float2 v1 = __half22float2(d_gh[sp.y]);
        float2 v2 = __half22float2(d_gh[sp.z]);
        float2 v3 = __half22float2(d_gh[sp.w]);
        red_add_v2(d_acc2 + 2 * (size_t)dp.x, v0);
        red_add_v2(d_acc2 + 2 * (size_t)dp.y, v1);
        red_add_v2(d_acc2 + 2 * (size_t)dp.z, v2);
        red_add_v2(d_acc2 + 2 * (size_t)dp.w, v3);
    } else {
        for (int k = 0; k < 4; k++) {
            int e = base + k;
            if (e < E) {
                int s = idx[e];
                int d = idx[(size_t)E + e];
                red_add_v2(d_acc2 + 2 * (size_t)d, __half22float2(d_gh[s]));
            }
        }
    }
}

// Final: out = dinv*(acc2 + self_f32) + b2
__global__ __launch_bounds__(256) void k_out(const float* __restrict__ b2,
                                             float* __restrict__ out, int n) {
    int i = blockIdx.x * blockDim.x + threadIdx.x;
    if (i >= n) return;
    float dv = d_dinv[i];
    float2 a = *(const float2*)(d_acc2 + 2 * (size_t)i);
    float2 g = *(const float2*)(d_g + 2 * (size_t)i);
    out[2 * (size_t)i + 0] = dv * (a.x + g.x) + __ldg(b2);
    out[2 * (size_t)i + 1] = dv * (a.y + g.y) + __ldg(b2 + 1);
}

extern "C" void kernel_launch(void* const* d_in, const int* in_sizes, int n_in,
                              void* d_out, int out_size) {
    const float* x  = (const float*)d_in[0];
    const int*   ei = (const int*)d_in[1];     // int32 (jax x64 disabled)
    const float* W1 = (const float*)d_in[2];
    const float* b1 = (const float*)d_in[3];
    const float* W2 = (const float*)d_in[4];
    const float* b2 = (const float*)d_in[5];
    float* out = (float*)d_out;

    int n = in_sizes[0] / 10;
    int E = in_sizes[1] / 2;

    const int TB = 256;
    int gn  = (n + TB - 1) / TB;
    int ge2 = ((E + 1) / 2 + TB - 1) / TB;
    int ge4 = ((E + 3) / 4 + TB - 1) / TB;

    k_zero_deg<<<gn,  TB>>>(n);
    k_deg     <<<ge4, TB>>>(ei + E, E);     // dst row
    k_scale   <<<gn,  TB>>>(x, n);
    k_scat1   <<<ge2, TB>>>(ei, E);
    k_node    <<<gn,  TB>>>(W1, b1, W2, n);
    k_scat2   <<<ge4, TB>>>(ei, E);
    k_out     <<<gn,  TB>>>(b2, out, n);
}